// round 8
// baseline (speedup 1.0000x reference)
#include <cuda_runtime.h>
#include <cstdint>
#include <math.h>

// Problem constants
#define BQ      4
#define NT      4096
#define CC      768
#define NHEADS  12
#define NPTS    4
#define HDIM    64
#define HIDDEN  3072
#define MROWS   (BQ*NT)          // 16384
#define SCALE_ATTN 0.125f        // 64^-0.5

// ---------------- scratch (device globals; no cudaMalloc allowed) ----------
__device__ float g_h[(size_t)MROWS * CC];          // ln1 out / ln2 out (reused)
__device__ float g_qkv[(size_t)MROWS * 3 * CC];    // qkv
__device__ float g_off[(size_t)MROWS * NHEADS * NPTS * 2];
__device__ float g_attn[(size_t)MROWS * CC];       // attention output
__device__ float g_mlp[(size_t)MROWS * HIDDEN];    // gelu(fc1)

// ---------------- LayerNorm ------------------------------------------------
__global__ __launch_bounds__(256) void layernorm_kernel(
    const float* __restrict__ x, const float* __restrict__ w,
    const float* __restrict__ b, float* __restrict__ out)
{
    int row = blockIdx.x;
    int t = threadIdx.x;
    const float* xr = x + (size_t)row * CC;
    float v0 = xr[t], v1 = xr[t + 256], v2 = xr[t + 512];
    float s  = v0 + v1 + v2;
    float sq = v0*v0 + v1*v1 + v2*v2;

    __shared__ float sh[16];
    #pragma unroll
    for (int o = 16; o > 0; o >>= 1) {
        s  += __shfl_xor_sync(0xffffffffu, s,  o);
        sq += __shfl_xor_sync(0xffffffffu, sq, o);
    }
    int wid = t >> 5, lane = t & 31;
    if (lane == 0) { sh[wid] = s; sh[8 + wid] = sq; }
    __syncthreads();
    if (t == 0) {
        float ts = 0.f, tq = 0.f;
        #pragma unroll
        for (int i = 0; i < 8; i++) { ts += sh[i]; tq += sh[8 + i]; }
        sh[0] = ts; sh[8] = tq;
    }
    __syncthreads();
    float mean = sh[0] * (1.0f / CC);
    float var  = sh[8] * (1.0f / CC) - mean * mean;
    float rstd = rsqrtf(var + 1e-5f);
    float* orow = out + (size_t)row * CC;
    orow[t]       = (v0 - mean) * rstd * w[t]       + b[t];
    orow[t + 256] = (v1 - mean) * rstd * w[t + 256] + b[t + 256];
    orow[t + 512] = (v2 - mean) * rstd * w[t + 512] + b[t + 512];
}

// ============================================================================
// TF32 mma.sync GEMM: C[M,N] = A[M,K] * W[N,K]^T + bias (+epilogue)
// Block tile 128x256x16, warp tile 64x64 (8 warps = 2M x 4N), fp32 bits fed
// directly as tf32 operands (truncation; no cvt). cp.async double-buffered.
// Requires M%128==0, N%256==0, K%16==0, lda==K.
// EPI: 0 = bias, 1 = bias + exact GELU, 2 = bias + residual add
// ============================================================================
#define TBM 128
#define TBN 256
#define TBK 16
#define TSTR 20   // smem row stride in floats (16 + 4 pad)

// dynamic smem layout in floats:
//  A0 @ 0      (128*20 = 2560)
//  A1 @ 2560
//  B0 @ 5120   (256*20 = 5120)
//  B1 @ 10240
#define SMF_A0 0
#define SMF_A1 2560
#define SMF_B0 5120
#define SMF_B1 10240
#define SM_BYTES ((10240 + 5120) * 4)   // 61440

__device__ __forceinline__ void cp_async16(void* smem_dst, const void* gmem_src) {
    uint32_t s = (uint32_t)__cvta_generic_to_shared(smem_dst);
    asm volatile("cp.async.cg.shared.global [%0], [%1], 16;\n" :: "r"(s), "l"(gmem_src));
}

template<int EPI>
__global__ __launch_bounds__(256) void tf32gemm_nt(
    const float* __restrict__ A,            // [M, K], lda == K
    const float* __restrict__ Bw,           // [N, K], K contiguous
    const float* __restrict__ bias,
    const float* __restrict__ Res, int ldr,
    float* __restrict__ C, int ldc,
    int K)
{
    extern __shared__ float smf[];

    const int t = threadIdx.x;
    const int rowTile = blockIdx.y * TBM;
    const int colTile = blockIdx.x * TBN;

    const int warp = t >> 5, lane = t & 31;
    const int wm = (warp & 1) * 64;        // 2 warps along M
    const int wn = (warp >> 1) * 64;       // 4 warps along N
    const int g  = lane >> 2;              // 0..7
    const int t4 = lane & 3;               // 0..3

    float acc[4][8][4];
    #pragma unroll
    for (int i = 0; i < 4; i++)
        #pragma unroll
        for (int j = 0; j < 8; j++)
            #pragma unroll
            for (int r = 0; r < 4; r++) acc[i][j][r] = 0.f;

    const int NK = K / TBK;
    const int Abase[2] = {SMF_A0, SMF_A1};
    const int Bbase[2] = {SMF_B0, SMF_B1};

    // cp.async: A = 512 x 16B chunks (2/thread), B = 1024 chunks (4/thread)
    auto load_tile = [&](int kt, int buf) {
        const int kk = kt * TBK;
        #pragma unroll
        for (int i = 0; i < 2; i++) {
            int c = t + i * 256;
            int row = c >> 2, kc = (c & 3) * 4;
            cp_async16(&smf[Abase[buf] + row * TSTR + kc],
                       A + (size_t)(rowTile + row) * K + kk + kc);
        }
        #pragma unroll
        for (int i = 0; i < 4; i++) {
            int c = t + i * 256;
            int row = c >> 2, kc = (c & 3) * 4;
            cp_async16(&smf[Bbase[buf] + row * TSTR + kc],
                       Bw + (size_t)(colTile + row) * K + kk + kc);
        }
        asm volatile("cp.async.commit_group;\n");
    };

    load_tile(0, 0);
    if (NK > 1) load_tile(1, 1);

    for (int kt = 0; kt < NK; kt++) {
        const int buf = kt & 1;
        if (kt + 1 < NK) asm volatile("cp.async.wait_group 1;\n");
        else             asm volatile("cp.async.wait_group 0;\n");
        __syncthreads();

        const float* As = &smf[Abase[buf]];
        const float* Bs = &smf[Bbase[buf]];

        #pragma unroll
        for (int ks = 0; ks < 2; ks++) {
            const int k0 = ks * 8;
            // A fragments: 4 x m16 (raw fp32 bits as tf32)
            uint32_t afr[4][4];
            #pragma unroll
            for (int i = 0; i < 4; i++) {
                int rr = wm + i * 16 + g;
                afr[i][0] = __float_as_uint(As[(rr    ) * TSTR + k0 + t4]);
                afr[i][1] = __float_as_uint(As[(rr + 8) * TSTR + k0 + t4]);
                afr[i][2] = __float_as_uint(As[(rr    ) * TSTR + k0 + t4 + 4]);
                afr[i][3] = __float_as_uint(As[(rr + 8) * TSTR + k0 + t4 + 4]);
            }
            // B fragments: 8 x n8
            uint32_t bfr[8][2];
            #pragma unroll
            for (int j = 0; j < 8; j++) {
                int cc = wn + j * 8 + g;
                bfr[j][0] = __float_as_uint(Bs[cc * TSTR + k0 + t4]);
                bfr[j][1] = __float_as_uint(Bs[cc * TSTR + k0 + t4 + 4]);
            }
            #pragma unroll
            for (int i = 0; i < 4; i++)
                #pragma unroll
                for (int j = 0; j < 8; j++) {
                    asm volatile(
                        "mma.sync.aligned.m16n8k8.row.col.f32.tf32.tf32.f32 "
                        "{%0,%1,%2,%3}, {%4,%5,%6,%7}, {%8,%9}, {%0,%1,%2,%3};\n"
                        : "+f"(acc[i][j][0]), "+f"(acc[i][j][1]),
                          "+f"(acc[i][j][2]), "+f"(acc[i][j][3])
                        : "r"(afr[i][0]), "r"(afr[i][1]), "r"(afr[i][2]), "r"(afr[i][3]),
                          "r"(bfr[j][0]), "r"(bfr[j][1]));
                }
        }
        __syncthreads();

        if (kt + 2 < NK) load_tile(kt + 2, buf);
    }

    // epilogue: acc[i][j] -> rows {wm+i*16+g, +8}, cols {wn+j*8+2*t4, +1}
    #pragma unroll
    for (int i = 0; i < 4; i++) {
        #pragma unroll
        for (int half = 0; half < 2; half++) {
            int r = rowTile + wm + i * 16 + g + half * 8;
            float* crow = C + (size_t)r * ldc;
            const float* rrow = (EPI == 2) ? (Res + (size_t)r * ldr) : nullptr;
            #pragma unroll
            for (int j = 0; j < 8; j++) {
                int cg = colTile + wn + j * 8 + t4 * 2;
                float v0 = acc[i][j][half * 2 + 0] + bias[cg];
                float v1 = acc[i][j][half * 2 + 1] + bias[cg + 1];
                if (EPI == 1) {
                    v0 = 0.5f * v0 * (1.0f + erff(v0 * 0.70710678118654752f));
                    v1 = 0.5f * v1 * (1.0f + erff(v1 * 0.70710678118654752f));
                }
                if (EPI == 2) { v0 += rrow[cg]; v1 += rrow[cg + 1]; }
                *(float2*)(crow + cg) = make_float2(v0, v1);
            }
        }
    }
}

// ---------------- fp32 SGEMM (small N=96 offsets GEMM) ---------------------
__global__ __launch_bounds__(256) void sgemm_nt(
    const float* __restrict__ A, int lda,
    const float* __restrict__ Bw,
    const float* __restrict__ bias,
    float* __restrict__ C, int ldc,
    int M, int N, int K)
{
    __shared__ float As[8][128];
    __shared__ float Bs[8][128];

    int t = threadIdx.x;
    int rowTile = blockIdx.y * 128;
    int colTile = blockIdx.x * 128;

    int ldRow = t >> 1;
    int ldCol = (t & 1) * 4;

    const float* Aptr = A + (size_t)(rowTile + ldRow) * lda + ldCol;
    bool bValid = (colTile + ldRow) < N;
    const float* Bptr = Bw + (size_t)(colTile + ldRow) * K + ldCol;

    int ty = t >> 4, tx = t & 15;
    float acc[8][8];
    #pragma unroll
    for (int i = 0; i < 8; i++)
        #pragma unroll
        for (int j = 0; j < 8; j++) acc[i][j] = 0.f;

    for (int k0 = 0; k0 < K; k0 += 8) {
        float4 av = *(const float4*)(Aptr + k0);
        float4 bv = bValid ? *(const float4*)(Bptr + k0)
                           : make_float4(0.f, 0.f, 0.f, 0.f);
        As[ldCol + 0][ldRow] = av.x; As[ldCol + 1][ldRow] = av.y;
        As[ldCol + 2][ldRow] = av.z; As[ldCol + 3][ldRow] = av.w;
        Bs[ldCol + 0][ldRow] = bv.x; Bs[ldCol + 1][ldRow] = bv.y;
        Bs[ldCol + 2][ldRow] = bv.z; Bs[ldCol + 3][ldRow] = bv.w;
        __syncthreads();

        #pragma unroll
        for (int k = 0; k < 8; k++) {
            float4 a0 = *(const float4*)&As[k][ty * 8];
            float4 a1 = *(const float4*)&As[k][ty * 8 + 4];
            float4 b0 = *(const float4*)&Bs[k][tx * 8];
            float4 b1 = *(const float4*)&Bs[k][tx * 8 + 4];
            float ar[8] = {a0.x, a0.y, a0.z, a0.w, a1.x, a1.y, a1.z, a1.w};
            float br[8] = {b0.x, b0.y, b0.z, b0.w, b1.x, b1.y, b1.z, b1.w};
            #pragma unroll
            for (int i = 0; i < 8; i++)
                #pragma unroll
                for (int j = 0; j < 8; j++)
                    acc[i][j] = fmaf(ar[i], br[j], acc[i][j]);
        }
        __syncthreads();
    }

    #pragma unroll
    for (int i = 0; i < 8; i++) {
        int r = rowTile + ty * 8 + i;
        float* crow = C + (size_t)r * ldc;
        #pragma unroll
        for (int j = 0; j < 8; j++) {
            int c = colTile + tx * 8 + j;
            if (c < N) crow[c] = acc[i][j] + bias[c];
        }
    }
}

// ---------------- deformable sampling + attention (4 heads / 128-thr block)-
__global__ __launch_bounds__(128) void attn_kernel(
    const float* __restrict__ qkv,    // [M, 2304]
    const float* __restrict__ off,    // [M, 96]
    const float* __restrict__ refp,   // [M, 2]
    float* __restrict__ out,          // [M, 768]
    const int* __restrict__ Hp, const int* __restrict__ Wp)
{
    int bn   = blockIdx.x;
    int head = blockIdx.y * 4 + (threadIdx.x >> 5);
    int lane = threadIdx.x & 31;
    int b = bn / NT;

    int H = *Hp, W = *Wp;
    float fW = (float)W, fH = (float)H;

    size_t qbase = (size_t)bn * (3 * CC) + head * HDIM;
    float q0 = qkv[qbase + lane];
    float q1 = qkv[qbase + lane + 32];

    float ref0 = refp[(size_t)bn * 2 + 0];
    float ref1 = refp[(size_t)bn * 2 + 1];

    const float* offp = off + (size_t)bn * (NHEADS * NPTS * 2) + head * (NPTS * 2);

    float dots[NPTS];
    float sv0[NPTS], sv1[NPTS];

    #pragma unroll
    for (int p = 0; p < NPTS; p++) {
        float o0 = offp[p * 2 + 0];
        float o1 = offp[p * 2 + 1];
        float gx = 2.0f * (ref0 + o0 / fW) - 1.0f;
        float gy = 2.0f * (ref1 + o1 / fH) - 1.0f;
        float x = ((gx + 1.0f) * fW - 1.0f) * 0.5f;
        float y = ((gy + 1.0f) * fH - 1.0f) * 0.5f;
        float x0f = floorf(x), y0f = floorf(y);
        float wx = x - x0f, wy = y - y0f;
        int x0 = (int)x0f, y0 = (int)y0f;

        float cw[4] = {(1.f - wx) * (1.f - wy), wx * (1.f - wy),
                       (1.f - wx) * wy,          wx * wy};
        int cx[4] = {x0, x0 + 1, x0,     x0 + 1};
        int cy[4] = {y0, y0,     y0 + 1, y0 + 1};

        float sk0 = 0.f, sk1 = 0.f, vv0 = 0.f, vv1 = 0.f;
        #pragma unroll
        for (int c = 0; c < 4; c++) {
            int ix = cx[c], iy = cy[c];
            if (ix >= 0 && ix < W && iy >= 0 && iy < H) {
                size_t rb = ((size_t)(b * NT + iy * W + ix)) * (3 * CC) + head * HDIM;
                const float* kp = qkv + rb + CC;
                const float* vp = qkv + rb + 2 * CC;
                float w = cw[c];
                sk0 = fmaf(w, kp[lane],      sk0);
                sk1 = fmaf(w, kp[lane + 32], sk1);
                vv0 = fmaf(w, vp[lane],      vv0);
                vv1 = fmaf(w, vp[lane + 32], vv1);
            }
        }
        sv0[p] = vv0; sv1[p] = vv1;

        float dot = q0 * sk0 + q1 * sk1;
        #pragma unroll
        for (int o = 16; o > 0; o >>= 1)
            dot += __shfl_xor_sync(0xffffffffu, dot, o);
        dots[p] = dot * SCALE_ATTN;
    }

    float mx = fmaxf(fmaxf(dots[0], dots[1]), fmaxf(dots[2], dots[3]));
    float e[NPTS], es = 0.f;
    #pragma unroll
    for (int p = 0; p < NPTS; p++) { e[p] = __expf(dots[p] - mx); es += e[p]; }
    float inv = 1.0f / es;

    float out0 = 0.f, out1 = 0.f;
    #pragma unroll
    for (int p = 0; p < NPTS; p++) {
        float a = e[p] * inv;
        out0 = fmaf(a, sv0[p], out0);
        out1 = fmaf(a, sv1[p], out1);
    }
    size_t ob = (size_t)bn * CC + head * HDIM;
    out[ob + lane]      = out0;
    out[ob + lane + 32] = out1;
}

// ---------------- launch ----------------------------------------------------
extern "C" void kernel_launch(void* const* d_in, const int* in_sizes, int n_in,
                              void* d_out, int out_size)
{
    const float* x      = (const float*)d_in[0];
    const float* refp   = (const float*)d_in[1];
    const float* n1w    = (const float*)d_in[2];
    const float* n1b    = (const float*)d_in[3];
    const float* qkv_w  = (const float*)d_in[4];
    const float* qkv_b  = (const float*)d_in[5];
    const float* off_w  = (const float*)d_in[6];
    const float* off_b  = (const float*)d_in[7];
    const float* proj_w = (const float*)d_in[8];
    const float* proj_b = (const float*)d_in[9];
    const float* n2w    = (const float*)d_in[10];
    const float* n2b    = (const float*)d_in[11];
    const float* fc1_w  = (const float*)d_in[12];
    const float* fc1_b  = (const float*)d_in[13];
    const float* fc2_w  = (const float*)d_in[14];
    const float* fc2_b  = (const float*)d_in[15];
    const int*   Hp     = (const int*)d_in[16];
    const int*   Wp     = (const int*)d_in[17];
    float* out = (float*)d_out;

    float* h    = nullptr; cudaGetSymbolAddress((void**)&h,    g_h);
    float* qkv  = nullptr; cudaGetSymbolAddress((void**)&qkv,  g_qkv);
    float* offb = nullptr; cudaGetSymbolAddress((void**)&offb, g_off);
    float* attn = nullptr; cudaGetSymbolAddress((void**)&attn, g_attn);
    float* mlp  = nullptr; cudaGetSymbolAddress((void**)&mlp,  g_mlp);

    static bool attr_done = false;
    if (!attr_done) {
        cudaFuncSetAttribute(tf32gemm_nt<0>, cudaFuncAttributeMaxDynamicSharedMemorySize, SM_BYTES);
        cudaFuncSetAttribute(tf32gemm_nt<1>, cudaFuncAttributeMaxDynamicSharedMemorySize, SM_BYTES);
        cudaFuncSetAttribute(tf32gemm_nt<2>, cudaFuncAttributeMaxDynamicSharedMemorySize, SM_BYTES);
        attr_done = true;
    }

    // 1) ln1: x -> h
    layernorm_kernel<<<MROWS, 256>>>(x, n1w, n1b, h);

    // 2) qkv = h @ qkv_w^T + b : [16384, 2304]
    {
        dim3 grid((3 * CC) / TBN, MROWS / TBM);
        tf32gemm_nt<0><<<grid, 256, SM_BYTES>>>(h, qkv_w, qkv_b,
                                                nullptr, 0, qkv, 3 * CC, CC);
    }

    // 3) offsets = q @ off_w^T + off_b : [16384, 96]  (small; fp32 path)
    {
        dim3 grid(1, MROWS / 128);
        sgemm_nt<<<grid, 256>>>(qkv, 3 * CC, off_w, off_b,
                                offb, NHEADS * NPTS * 2,
                                MROWS, NHEADS * NPTS * 2, CC);
    }

    // 4) deformable sampling + attention -> attn [16384, 768]
    {
        dim3 grid(BQ * NT, NHEADS / 4);
        attn_kernel<<<grid, 128>>>(qkv, offb, refp, attn, Hp, Wp);
    }

    // 5) x1 = x + attn @ proj_w^T + proj_b -> out
    {
        dim3 grid(CC / TBN, MROWS / TBM);
        tf32gemm_nt<2><<<grid, 256, SM_BYTES>>>(attn, proj_w, proj_b,
                                                x, CC, out, CC, CC);
    }

    // 6) ln2: out -> h
    layernorm_kernel<<<MROWS, 256>>>(out, n2w, n2b, h);

    // 7) m = gelu(h @ fc1_w^T + fc1_b) -> mlp [16384, 3072]
    {
        dim3 grid(HIDDEN / TBN, MROWS / TBM);
        tf32gemm_nt<1><<<grid, 256, SM_BYTES>>>(h, fc1_w, fc1_b,
                                                nullptr, 0, mlp, HIDDEN, CC);
    }

    // 8) out = out + mlp @ fc2_w^T + fc2_b
    {
        dim3 grid(CC / TBN, MROWS / TBM);
        tf32gemm_nt<2><<<grid, 256, SM_BYTES>>>(mlp, fc2_w, fc2_b,
                                                out, CC, out, CC, HIDDEN);
    }
}

// round 9
// speedup vs baseline: 1.6031x; 1.6031x over previous
#include <cuda_runtime.h>
#include <cuda_fp16.h>
#include <cstdint>
#include <math.h>

// Problem constants
#define BQ      4
#define NT      4096
#define CC      768
#define NHEADS  12
#define NPTS    4
#define HDIM    64
#define HIDDEN  3072
#define MROWS   (BQ*NT)          // 16384
#define SCALE_ATTN 0.125f        // 64^-0.5

// ---------------- scratch (device globals; no cudaMalloc allowed) ----------
__device__ __half g_h[(size_t)MROWS * CC];          // ln out (fp16, GEMM A operand)
__device__ float  g_qkv[(size_t)MROWS * 3 * CC];    // qkv (fp32: attn sampling needs it)
__device__ float  g_off[(size_t)MROWS * NHEADS * NPTS * 2];
__device__ __half g_attn[(size_t)MROWS * CC];       // attention output (fp16 A operand)
__device__ __half g_mlp[(size_t)MROWS * HIDDEN];    // gelu(fc1) (fp16 A operand)
// fp16 weight copies (converted once per launch)
__device__ __half g_wqkv[(size_t)3 * CC * CC];
__device__ __half g_wproj[(size_t)CC * CC];
__device__ __half g_wfc1[(size_t)HIDDEN * CC];
__device__ __half g_wfc2[(size_t)CC * HIDDEN];

// ---------------- weight conversion fp32 -> fp16 ---------------------------
__global__ __launch_bounds__(256) void wconv_kernel(
    const float* __restrict__ src, __half* __restrict__ dst, int n4)
{
    int i = blockIdx.x * 256 + threadIdx.x;
    if (i < n4) {
        float4 v = ((const float4*)src)[i];
        __half2 h0 = __floats2half2_rn(v.x, v.y);
        __half2 h1 = __floats2half2_rn(v.z, v.w);
        ((uint2*)dst)[i] = make_uint2(*(uint32_t*)&h0, *(uint32_t*)&h1);
    }
}

// ---------------- LayerNorm: fp32 in -> fp16 out ---------------------------
__global__ __launch_bounds__(256) void layernorm_kernel(
    const float* __restrict__ x, const float* __restrict__ w,
    const float* __restrict__ b, __half* __restrict__ out)
{
    int row = blockIdx.x;
    int t = threadIdx.x;
    const float* xr = x + (size_t)row * CC;
    float v0 = xr[t], v1 = xr[t + 256], v2 = xr[t + 512];
    float s  = v0 + v1 + v2;
    float sq = v0*v0 + v1*v1 + v2*v2;

    __shared__ float sh[16];
    #pragma unroll
    for (int o = 16; o > 0; o >>= 1) {
        s  += __shfl_xor_sync(0xffffffffu, s,  o);
        sq += __shfl_xor_sync(0xffffffffu, sq, o);
    }
    int wid = t >> 5, lane = t & 31;
    if (lane == 0) { sh[wid] = s; sh[8 + wid] = sq; }
    __syncthreads();
    if (t == 0) {
        float ts = 0.f, tq = 0.f;
        #pragma unroll
        for (int i = 0; i < 8; i++) { ts += sh[i]; tq += sh[8 + i]; }
        sh[0] = ts; sh[8] = tq;
    }
    __syncthreads();
    float mean = sh[0] * (1.0f / CC);
    float var  = sh[8] * (1.0f / CC) - mean * mean;
    float rstd = rsqrtf(var + 1e-5f);
    __half* orow = out + (size_t)row * CC;
    orow[t]       = __float2half_rn((v0 - mean) * rstd * w[t]       + b[t]);
    orow[t + 256] = __float2half_rn((v1 - mean) * rstd * w[t + 256] + b[t + 256]);
    orow[t + 512] = __float2half_rn((v2 - mean) * rstd * w[t + 512] + b[t + 512]);
}

// ============================================================================
// FP16 mma.sync GEMM: C[M,N] = A[M,K] * W[N,K]^T + bias (+epilogue)
// A, W in fp16; fp32 accumulate. Block tile 128x256x32, warp tile 64x64
// (8 warps = 2M x 4N), mma.m16n8k16, cp.async double-buffered.
// Requires M%128==0, N%256==0, K%32==0, lda==K.
// EPI: 0 = bias -> float C, 1 = bias+GELU -> half C, 2 = bias+residual -> float C
// ============================================================================
#define HSTR 40   // smem row stride in halves (32 + 8 pad) -> conflict-free u32 LDS

// dynamic smem layout in halves:
#define HS_A0 0        // 128*40 = 5120
#define HS_A1 5120
#define HS_B0 10240    // 256*40 = 10240
#define HS_B1 20480
#define HSM_BYTES ((20480 + 10240) * 2)   // 61440

__device__ __forceinline__ void cp_async16(void* smem_dst, const void* gmem_src) {
    uint32_t s = (uint32_t)__cvta_generic_to_shared(smem_dst);
    asm volatile("cp.async.cg.shared.global [%0], [%1], 16;\n" :: "r"(s), "l"(gmem_src));
}

template<int EPI, typename OutT>
__global__ __launch_bounds__(256) void hgemm_nt(
    const __half* __restrict__ A,           // [M, K], lda == K
    const __half* __restrict__ Bw,          // [N, K], K contiguous
    const float* __restrict__ bias,
    const float* __restrict__ Res, int ldr,
    OutT* __restrict__ C, int ldc,
    int K)
{
    extern __shared__ __half smh[];

    const int t = threadIdx.x;
    const int rowTile = blockIdx.y * 128;
    const int colTile = blockIdx.x * 256;

    const int warp = t >> 5, lane = t & 31;
    const int wm = (warp & 1) * 64;        // 2 warps along M
    const int wn = (warp >> 1) * 64;       // 4 warps along N
    const int g  = lane >> 2;              // 0..7
    const int t4 = lane & 3;               // 0..3

    float acc[4][8][4];
    #pragma unroll
    for (int i = 0; i < 4; i++)
        #pragma unroll
        for (int j = 0; j < 8; j++)
            #pragma unroll
            for (int r = 0; r < 4; r++) acc[i][j][r] = 0.f;

    const int NK = K / 32;
    const int Abase[2] = {HS_A0, HS_A1};
    const int Bbase[2] = {HS_B0, HS_B1};

    // A tile: 128 rows x 32 halves = 512 x 16B chunks (2/thread)
    // B tile: 256 rows x 32 halves = 1024 chunks (4/thread)
    auto load_tile = [&](int kt, int buf) {
        const int kk = kt * 32;
        #pragma unroll
        for (int i = 0; i < 2; i++) {
            int c = t + i * 256;
            int row = c >> 2, kc = (c & 3) * 8;
            cp_async16(&smh[Abase[buf] + row * HSTR + kc],
                       A + (size_t)(rowTile + row) * K + kk + kc);
        }
        #pragma unroll
        for (int i = 0; i < 4; i++) {
            int c = t + i * 256;
            int row = c >> 2, kc = (c & 3) * 8;
            cp_async16(&smh[Bbase[buf] + row * HSTR + kc],
                       Bw + (size_t)(colTile + row) * K + kk + kc);
        }
        asm volatile("cp.async.commit_group;\n");
    };

    load_tile(0, 0);
    if (NK > 1) load_tile(1, 1);

    for (int kt = 0; kt < NK; kt++) {
        const int buf = kt & 1;
        if (kt + 1 < NK) asm volatile("cp.async.wait_group 1;\n");
        else             asm volatile("cp.async.wait_group 0;\n");
        __syncthreads();

        const __half* As = &smh[Abase[buf]];
        const __half* Bs = &smh[Bbase[buf]];

        #pragma unroll
        for (int ks = 0; ks < 2; ks++) {
            const int k0 = ks * 16;
            // A fragments: 4 x m16 tiles, mma.m16n8k16 layout
            uint32_t afr[4][4];
            #pragma unroll
            for (int i = 0; i < 4; i++) {
                int rr = wm + i * 16 + g;
                afr[i][0] = *(const uint32_t*)&As[(rr    ) * HSTR + k0 + 2 * t4];
                afr[i][1] = *(const uint32_t*)&As[(rr + 8) * HSTR + k0 + 2 * t4];
                afr[i][2] = *(const uint32_t*)&As[(rr    ) * HSTR + k0 + 2 * t4 + 8];
                afr[i][3] = *(const uint32_t*)&As[(rr + 8) * HSTR + k0 + 2 * t4 + 8];
            }
            // B fragments: 8 x n8 tiles
            uint32_t bfr[8][2];
            #pragma unroll
            for (int j = 0; j < 8; j++) {
                int cc = wn + j * 8 + g;
                bfr[j][0] = *(const uint32_t*)&Bs[cc * HSTR + k0 + 2 * t4];
                bfr[j][1] = *(const uint32_t*)&Bs[cc * HSTR + k0 + 2 * t4 + 8];
            }
            #pragma unroll
            for (int i = 0; i < 4; i++)
                #pragma unroll
                for (int j = 0; j < 8; j++) {
                    asm volatile(
                        "mma.sync.aligned.m16n8k16.row.col.f32.f16.f16.f32 "
                        "{%0,%1,%2,%3}, {%4,%5,%6,%7}, {%8,%9}, {%0,%1,%2,%3};\n"
                        : "+f"(acc[i][j][0]), "+f"(acc[i][j][1]),
                          "+f"(acc[i][j][2]), "+f"(acc[i][j][3])
                        : "r"(afr[i][0]), "r"(afr[i][1]), "r"(afr[i][2]), "r"(afr[i][3]),
                          "r"(bfr[j][0]), "r"(bfr[j][1]));
                }
        }
        __syncthreads();

        if (kt + 2 < NK) load_tile(kt + 2, buf);
    }

    // epilogue: acc[i][j] -> rows {wm+i*16+g, +8}, cols {wn+j*8+2*t4, +1}
    #pragma unroll
    for (int i = 0; i < 4; i++) {
        #pragma unroll
        for (int half = 0; half < 2; half++) {
            int r = rowTile + wm + i * 16 + g + half * 8;
            OutT* crow = C + (size_t)r * ldc;
            const float* rrow = (EPI == 2) ? (Res + (size_t)r * ldr) : nullptr;
            #pragma unroll
            for (int j = 0; j < 8; j++) {
                int cg = colTile + wn + j * 8 + t4 * 2;
                float v0 = acc[i][j][half * 2 + 0] + bias[cg];
                float v1 = acc[i][j][half * 2 + 1] + bias[cg + 1];
                if (EPI == 1) {
                    v0 = 0.5f * v0 * (1.0f + erff(v0 * 0.70710678118654752f));
                    v1 = 0.5f * v1 * (1.0f + erff(v1 * 0.70710678118654752f));
                }
                if (EPI == 2) { v0 += rrow[cg]; v1 += rrow[cg + 1]; }
                if (sizeof(OutT) == 2) {
                    __half2 hv = __floats2half2_rn(v0, v1);
                    *(__half2*)((__half*)crow + cg) = hv;
                } else {
                    *(float2*)((float*)crow + cg) = make_float2(v0, v1);
                }
            }
        }
    }
}

// ---------------- fp32 SGEMM (small N=96 offsets GEMM) ---------------------
__global__ __launch_bounds__(256) void sgemm_nt(
    const float* __restrict__ A, int lda,
    const float* __restrict__ Bw,
    const float* __restrict__ bias,
    float* __restrict__ C, int ldc,
    int M, int N, int K)
{
    __shared__ float As[8][128];
    __shared__ float Bs[8][128];

    int t = threadIdx.x;
    int rowTile = blockIdx.y * 128;
    int colTile = blockIdx.x * 128;

    int ldRow = t >> 1;
    int ldCol = (t & 1) * 4;

    const float* Aptr = A + (size_t)(rowTile + ldRow) * lda + ldCol;
    bool bValid = (colTile + ldRow) < N;
    const float* Bptr = Bw + (size_t)(colTile + ldRow) * K + ldCol;

    int ty = t >> 4, tx = t & 15;
    float acc[8][8];
    #pragma unroll
    for (int i = 0; i < 8; i++)
        #pragma unroll
        for (int j = 0; j < 8; j++) acc[i][j] = 0.f;

    for (int k0 = 0; k0 < K; k0 += 8) {
        float4 av = *(const float4*)(Aptr + k0);
        float4 bv = bValid ? *(const float4*)(Bptr + k0)
                           : make_float4(0.f, 0.f, 0.f, 0.f);
        As[ldCol + 0][ldRow] = av.x; As[ldCol + 1][ldRow] = av.y;
        As[ldCol + 2][ldRow] = av.z; As[ldCol + 3][ldRow] = av.w;
        Bs[ldCol + 0][ldRow] = bv.x; Bs[ldCol + 1][ldRow] = bv.y;
        Bs[ldCol + 2][ldRow] = bv.z; Bs[ldCol + 3][ldRow] = bv.w;
        __syncthreads();

        #pragma unroll
        for (int k = 0; k < 8; k++) {
            float4 a0 = *(const float4*)&As[k][ty * 8];
            float4 a1 = *(const float4*)&As[k][ty * 8 + 4];
            float4 b0 = *(const float4*)&Bs[k][tx * 8];
            float4 b1 = *(const float4*)&Bs[k][tx * 8 + 4];
            float ar[8] = {a0.x, a0.y, a0.z, a0.w, a1.x, a1.y, a1.z, a1.w};
            float br[8] = {b0.x, b0.y, b0.z, b0.w, b1.x, b1.y, b1.z, b1.w};
            #pragma unroll
            for (int i = 0; i < 8; i++)
                #pragma unroll
                for (int j = 0; j < 8; j++)
                    acc[i][j] = fmaf(ar[i], br[j], acc[i][j]);
        }
        __syncthreads();
    }

    #pragma unroll
    for (int i = 0; i < 8; i++) {
        int r = rowTile + ty * 8 + i;
        float* crow = C + (size_t)r * ldc;
        #pragma unroll
        for (int j = 0; j < 8; j++) {
            int c = colTile + tx * 8 + j;
            if (c < N) crow[c] = acc[i][j] + bias[c];
        }
    }
}

// ---------------- deformable sampling + attention (4 heads / 128-thr block)-
__global__ __launch_bounds__(128) void attn_kernel(
    const float* __restrict__ qkv,    // [M, 2304]
    const float* __restrict__ off,    // [M, 96]
    const float* __restrict__ refp,   // [M, 2]
    __half* __restrict__ out,         // [M, 768] fp16
    const int* __restrict__ Hp, const int* __restrict__ Wp)
{
    int bn   = blockIdx.x;
    int head = blockIdx.y * 4 + (threadIdx.x >> 5);
    int lane = threadIdx.x & 31;
    int b = bn / NT;

    int H = *Hp, W = *Wp;
    float fW = (float)W, fH = (float)H;

    size_t qbase = (size_t)bn * (3 * CC) + head * HDIM;
    float q0 = qkv[qbase + lane];
    float q1 = qkv[qbase + lane + 32];

    float ref0 = refp[(size_t)bn * 2 + 0];
    float ref1 = refp[(size_t)bn * 2 + 1];

    const float* offp = off + (size_t)bn * (NHEADS * NPTS * 2) + head * (NPTS * 2);

    float dots[NPTS];
    float sv0[NPTS], sv1[NPTS];

    #pragma unroll
    for (int p = 0; p < NPTS; p++) {
        float o0 = offp[p * 2 + 0];
        float o1 = offp[p * 2 + 1];
        float gx = 2.0f * (ref0 + o0 / fW) - 1.0f;
        float gy = 2.0f * (ref1 + o1 / fH) - 1.0f;
        float x = ((gx + 1.0f) * fW - 1.0f) * 0.5f;
        float y = ((gy + 1.0f) * fH - 1.0f) * 0.5f;
        float x0f = floorf(x), y0f = floorf(y);
        float wx = x - x0f, wy = y - y0f;
        int x0 = (int)x0f, y0 = (int)y0f;

        float cw[4] = {(1.f - wx) * (1.f - wy), wx * (1.f - wy),
                       (1.f - wx) * wy,          wx * wy};
        int cx[4] = {x0, x0 + 1, x0,     x0 + 1};
        int cy[4] = {y0, y0,     y0 + 1, y0 + 1};

        float sk0 = 0.f, sk1 = 0.f, vv0 = 0.f, vv1 = 0.f;
        #pragma unroll
        for (int c = 0; c < 4; c++) {
            int ix = cx[c], iy = cy[c];
            if (ix >= 0 && ix < W && iy >= 0 && iy < H) {
                size_t rb = ((size_t)(b * NT + iy * W + ix)) * (3 * CC) + head * HDIM;
                const float* kp = qkv + rb + CC;
                const float* vp = qkv + rb + 2 * CC;
                float w = cw[c];
                sk0 = fmaf(w, kp[lane],      sk0);
                sk1 = fmaf(w, kp[lane + 32], sk1);
                vv0 = fmaf(w, vp[lane],      vv0);
                vv1 = fmaf(w, vp[lane + 32], vv1);
            }
        }
        sv0[p] = vv0; sv1[p] = vv1;

        float dot = q0 * sk0 + q1 * sk1;
        #pragma unroll
        for (int o = 16; o > 0; o >>= 1)
            dot += __shfl_xor_sync(0xffffffffu, dot, o);
        dots[p] = dot * SCALE_ATTN;
    }

    float mx = fmaxf(fmaxf(dots[0], dots[1]), fmaxf(dots[2], dots[3]));
    float e[NPTS], es = 0.f;
    #pragma unroll
    for (int p = 0; p < NPTS; p++) { e[p] = __expf(dots[p] - mx); es += e[p]; }
    float inv = 1.0f / es;

    float out0 = 0.f, out1 = 0.f;
    #pragma unroll
    for (int p = 0; p < NPTS; p++) {
        float a = e[p] * inv;
        out0 = fmaf(a, sv0[p], out0);
        out1 = fmaf(a, sv1[p], out1);
    }
    size_t ob = (size_t)bn * CC + head * HDIM;
    out[ob + lane]      = __float2half_rn(out0);
    out[ob + lane + 32] = __float2half_rn(out1);
}

// ---------------- launch ----------------------------------------------------
extern "C" void kernel_launch(void* const* d_in, const int* in_sizes, int n_in,
                              void* d_out, int out_size)
{
    const float* x      = (const float*)d_in[0];
    const float* refp   = (const float*)d_in[1];
    const float* n1w    = (const float*)d_in[2];
    const float* n1b    = (const float*)d_in[3];
    const float* qkv_w  = (const float*)d_in[4];
    const float* qkv_b  = (const float*)d_in[5];
    const float* off_w  = (const float*)d_in[6];
    const float* off_b  = (const float*)d_in[7];
    const float* proj_w = (const float*)d_in[8];
    const float* proj_b = (const float*)d_in[9];
    const float* n2w    = (const float*)d_in[10];
    const float* n2b    = (const float*)d_in[11];
    const float* fc1_w  = (const float*)d_in[12];
    const float* fc1_b  = (const float*)d_in[13];
    const float* fc2_w  = (const float*)d_in[14];
    const float* fc2_b  = (const float*)d_in[15];
    const int*   Hp     = (const int*)d_in[16];
    const int*   Wp     = (const int*)d_in[17];
    float* out = (float*)d_out;

    __half* h    = nullptr; cudaGetSymbolAddress((void**)&h,    g_h);
    float*  qkv  = nullptr; cudaGetSymbolAddress((void**)&qkv,  g_qkv);
    float*  offb = nullptr; cudaGetSymbolAddress((void**)&offb, g_off);
    __half* attn = nullptr; cudaGetSymbolAddress((void**)&attn, g_attn);
    __half* mlp  = nullptr; cudaGetSymbolAddress((void**)&mlp,  g_mlp);
    __half* wqkv = nullptr; cudaGetSymbolAddress((void**)&wqkv, g_wqkv);
    __half* wproj= nullptr; cudaGetSymbolAddress((void**)&wproj,g_wproj);
    __half* wfc1 = nullptr; cudaGetSymbolAddress((void**)&wfc1, g_wfc1);
    __half* wfc2 = nullptr; cudaGetSymbolAddress((void**)&wfc2, g_wfc2);

    static bool attr_done = false;
    if (!attr_done) {
        cudaFuncSetAttribute((const void*)hgemm_nt<0,float>,  cudaFuncAttributeMaxDynamicSharedMemorySize, HSM_BYTES);
        cudaFuncSetAttribute((const void*)hgemm_nt<1,__half>, cudaFuncAttributeMaxDynamicSharedMemorySize, HSM_BYTES);
        cudaFuncSetAttribute((const void*)hgemm_nt<2,float>,  cudaFuncAttributeMaxDynamicSharedMemorySize, HSM_BYTES);
        attr_done = true;
    }

    // 0) convert weights to fp16 (tiny; same every call -> deterministic)
    {
        int n;
        n = 3 * CC * CC / 4;    wconv_kernel<<<(n + 255) / 256, 256>>>(qkv_w,  wqkv,  n);
        n = CC * CC / 4;        wconv_kernel<<<(n + 255) / 256, 256>>>(proj_w, wproj, n);
        n = HIDDEN * CC / 4;    wconv_kernel<<<(n + 255) / 256, 256>>>(fc1_w,  wfc1,  n);
        n = CC * HIDDEN / 4;    wconv_kernel<<<(n + 255) / 256, 256>>>(fc2_w,  wfc2,  n);
    }

    // 1) ln1: x -> h (fp16)
    layernorm_kernel<<<MROWS, 256>>>(x, n1w, n1b, h);

    // 2) qkv = h @ qkv_w^T + b : [16384, 2304] fp32 out
    {
        dim3 grid((3 * CC) / 256, MROWS / 128);
        hgemm_nt<0,float><<<grid, 256, HSM_BYTES>>>(h, wqkv, qkv_b,
                                                    nullptr, 0, qkv, 3 * CC, CC);
    }

    // 3) offsets = q @ off_w^T + off_b : [16384, 96]  (small; fp32 path)
    {
        dim3 grid(1, MROWS / 128);
        sgemm_nt<<<grid, 256>>>(qkv, 3 * CC, off_w, off_b,
                                offb, NHEADS * NPTS * 2,
                                MROWS, NHEADS * NPTS * 2, CC);
    }

    // 4) deformable sampling + attention -> attn [16384, 768] fp16
    {
        dim3 grid(BQ * NT, NHEADS / 4);
        attn_kernel<<<grid, 128>>>(qkv, offb, refp, attn, Hp, Wp);
    }

    // 5) x1 = x + attn @ proj_w^T + proj_b -> out (fp32)
    {
        dim3 grid(CC / 256, MROWS / 128);
        hgemm_nt<2,float><<<grid, 256, HSM_BYTES>>>(attn, wproj, proj_b,
                                                    x, CC, out, CC, CC);
    }

    // 6) ln2: out -> h (fp16)
    layernorm_kernel<<<MROWS, 256>>>(out, n2w, n2b, h);

    // 7) m = gelu(h @ fc1_w^T + fc1_b) -> mlp [16384, 3072] fp16
    {
        dim3 grid(HIDDEN / 256, MROWS / 128);
        hgemm_nt<1,__half><<<grid, 256, HSM_BYTES>>>(h, wfc1, fc1_b,
                                                     nullptr, 0, mlp, HIDDEN, CC);
    }

    // 8) out = out + mlp @ fc2_w^T + fc2_b (fp32)
    {
        dim3 grid(CC / 256, MROWS / 128);
        hgemm_nt<2,float><<<grid, 256, HSM_BYTES>>>(mlp, wfc2, fc2_b,
                                                    out, CC, out, CC, HIDDEN);
    }
}